// round 8
// baseline (speedup 1.0000x reference)
#include <cuda_runtime.h>
#include <cuda_bf16.h>
#include <math.h>
#include <stdint.h>

// NCE loss: scores(16384x104) = inp(16384x512) @ noise_emb^T via HMMA bf16.
// Grid=128 CTAs x 256 thr, 128 tokens/CTA, 1 CTA/SM.
// Target-emb rows staged through smem via cp.async.cg (3-buf ring, ~64KB in
// flight) and the target dot is fused into the GEMM k-loop using the A
// fragments already in registers (fp32 exact). B (104x512 bf16) in smem,
// XOR-swizzled for ldmatrix.

#define E      512
#define NRR    100
#define NP     104          // 13 * 8
#define NT     13
#define TPB    256
#define GRID1  128
#define NTOK   16384

#define TROW   272          // target-row stride in tbuf (16B aligned, anti-conflict)
#define TBUF   34816        // 128 * 272
#define SM_B     0          // 104 * 1024
#define SM_SC    106496     // 104 floats
#define SM_TC    106912     // 128 floats: bias-logn-csub per token
#define SM_TGT   107424     // 128 ints
#define SM_RED   107936     // 8 floats
#define SM_FLAG  108000
#define SM_TB    108032     // 3 * 34816
#define SM_TOTAL (SM_TB + 3 * TBUF)   // 212480

__device__ float        g_partials[GRID1];
__device__ unsigned int g_counter;

__device__ __forceinline__ float softplus_fast(float x) {
    return fmaxf(x, 0.0f) + __logf(1.0f + __expf(-fabsf(x)));
}
__device__ __forceinline__ uint32_t smem_u32(const void* p) {
    uint32_t a;
    asm("{ .reg .u64 t; cvta.to.shared.u64 t, %1; cvt.u32.u64 %0, t; }"
        : "=r"(a) : "l"(p));
    return a;
}
__device__ __forceinline__ uint32_t bf2(float lo, float hi) {
    uint32_t r;
    asm("cvt.rn.bf16x2.f32 %0, %1, %2;" : "=r"(r) : "f"(hi), "f"(lo));
    return r;
}
__device__ __forceinline__ void mma16816(float* d,
        uint32_t a0, uint32_t a1, uint32_t a2, uint32_t a3,
        uint32_t b0, uint32_t b1) {
    asm volatile("mma.sync.aligned.m16n8k16.row.col.f32.bf16.bf16.f32 "
        "{%0,%1,%2,%3}, {%4,%5,%6,%7}, {%8,%9}, {%0,%1,%2,%3};"
        : "+f"(d[0]), "+f"(d[1]), "+f"(d[2]), "+f"(d[3])
        : "r"(a0), "r"(a1), "r"(a2), "r"(a3), "r"(b0), "r"(b1));
}

__global__ void __launch_bounds__(TPB, 1)
nce_hmma(const float* __restrict__ inp,
         const float* __restrict__ emb,
         const float* __restrict__ bias,
         const float* __restrict__ logn,
         const int*   __restrict__ target,
         const int*   __restrict__ noise_idx,
         float csub, float* __restrict__ out)
{
    extern __shared__ char smem[];
    const uint32_t sb = smem_u32(smem);
    const int tid = threadIdx.x, warp = tid >> 5, lane = tid & 31;
    const int gid = lane >> 2, ctg = lane & 3;
    float* sC    = (float*)(smem + SM_SC);
    float* sTC   = (float*)(smem + SM_TC);
    int*   sTgt  = (int*)(smem + SM_TGT);
    float* sRed  = (float*)(smem + SM_RED);
    int*   sFlag = (int*)(smem + SM_FLAG);
    const int tokBase = blockIdx.x * 128;

    // ---- per-token constants + target ids
    if (tid < 128) {
        int tg = target[tokBase + tid];
        sTgt[tid] = tg;
        sTC[tid]  = bias[tg] - logn[tg] - csub;
    }
    if (tid < NP) {
        float cv = -INFINITY;              // pad cols 100..103 -> softplus 0
        if (tid < NRR) {
            int nid = noise_idx[tid];
            cv = bias[nid] - logn[nid] - csub;
        }
        sC[tid] = cv;
    }
    __syncthreads();

    // ---- cp.async stage of target k-chunk c: all 128 rows x 64 f32
    auto stageT = [&](int c) {
        const uint32_t dbase = sb + (uint32_t)(SM_TB + (c % 3) * TBUF);
        #pragma unroll
        for (int i = 0; i < 8; ++i) {
            int chunk = tid + i * TPB;      // 0..2047
            int j = chunk >> 4;             // row
            int w = chunk & 15;             // 16B unit within 64-float slice
            const char* src = (const char*)(emb + (size_t)sTgt[j] * E + c * 64) + w * 16;
            uint32_t sa = dbase + (uint32_t)(j * TROW + w * 16);
            asm volatile("cp.async.cg.shared.global [%0], [%1], 16;" :: "r"(sa), "l"(src));
        }
        asm volatile("cp.async.commit_group;");
    };
    stageT(0);
    stageT(1);

    // ---- stage B: 104 x 512 bf16, 16B chunks XOR-swizzled per row
    for (int i = tid; i < NP * 64; i += TPB) {
        int n = i >> 6, c = i & 63;
        uint4 pk = make_uint4(0u, 0u, 0u, 0u);
        if (n < NRR) {
            int nid = noise_idx[n];
            const float4* r = (const float4*)(emb + (size_t)nid * E) + (c << 1);
            float4 v0 = r[0], v1 = r[1];
            pk.x = bf2(v0.x, v0.y); pk.y = bf2(v0.z, v0.w);
            pk.z = bf2(v1.x, v1.y); pk.w = bf2(v1.z, v1.w);
        }
        *(uint4*)(smem + SM_B + n * 1024 + ((c ^ (n & 7)) << 4)) = pk;
    }
    __syncthreads();

    // ---- GEMM accumulators + fused target partials
    float acc[NT][4];
    #pragma unroll
    for (int t = 0; t < NT; ++t)
        #pragma unroll
        for (int r = 0; r < 4; ++r) acc[t][r] = 0.0f;
    float tacc0 = 0.0f, tacc1 = 0.0f;

    int nb[7], m7[7];
    #pragma unroll
    for (int p = 0; p < 6; ++p) {
        int n = (2 * p + (lane >> 4)) * 8 + (lane & 7);
        nb[p] = n * 1024; m7[p] = n & 7;
    }
    { int n = 96 + (lane & 7); nb[6] = n * 1024; m7[6] = n & 7; }
    const int khB = (lane >> 3) & 1;

    const float* aR0 = inp + (size_t)(tokBase + warp * 16 + gid) * E + ctg * 2;
    const float* aR1 = aR0 + 8 * E;

    // A prefetch depth 2
    float2 f[2][4];
    #pragma unroll
    for (int d = 0; d < 2; ++d) {
        f[d][0] = *(const float2*)(aR0 + d * 16);
        f[d][1] = *(const float2*)(aR1 + d * 16);
        f[d][2] = *(const float2*)(aR0 + d * 16 + 8);
        f[d][3] = *(const float2*)(aR1 + d * 16 + 8);
    }

    const int trow0 = (warp * 16 + gid) * TROW + ctg * 8;

    #pragma unroll 1
    for (int c = 0; c < 8; ++c) {
        // chunk boundary: ensure target chunk c landed; recycle buffers
        if (c == 7) asm volatile("cp.async.wait_group 0;" ::: "memory");
        else        asm volatile("cp.async.wait_group 1;" ::: "memory");
        __syncthreads();
        if (c + 2 < 8) stageT(c + 2);

        const char* tb = smem + SM_TB + (c % 3) * TBUF;

        #pragma unroll
        for (int kl = 0; kl < 4; ++kl) {
            const int ks = c * 4 + kl;
            float2 g0 = f[ks & 1][0], g1 = f[ks & 1][1];
            float2 g2 = f[ks & 1][2], g3 = f[ks & 1][3];
            if (ks + 2 < 32) {
                f[ks & 1][0] = *(const float2*)(aR0 + (ks + 2) * 16);
                f[ks & 1][1] = *(const float2*)(aR1 + (ks + 2) * 16);
                f[ks & 1][2] = *(const float2*)(aR0 + (ks + 2) * 16 + 8);
                f[ks & 1][3] = *(const float2*)(aR1 + (ks + 2) * 16 + 8);
            }
            uint32_t a0 = bf2(g0.x, g0.y), a1 = bf2(g1.x, g1.y);
            uint32_t a2 = bf2(g2.x, g2.y), a3 = bf2(g3.x, g3.y);

            // fused target dot (fp32 exact) from staged smem
            {
                const char* tp = tb + trow0 + kl * 64;
                float2 T0 = *(const float2*)(tp);
                float2 T2 = *(const float2*)(tp + 32);
                float2 T1 = *(const float2*)(tp + 8 * TROW);
                float2 T3 = *(const float2*)(tp + 8 * TROW + 32);
                tacc0 = fmaf(g0.x, T0.x, tacc0); tacc0 = fmaf(g0.y, T0.y, tacc0);
                tacc0 = fmaf(g2.x, T2.x, tacc0); tacc0 = fmaf(g2.y, T2.y, tacc0);
                tacc1 = fmaf(g1.x, T1.x, tacc1); tacc1 = fmaf(g1.y, T1.y, tacc1);
                tacc1 = fmaf(g3.x, T3.x, tacc1); tacc1 = fmaf(g3.y, T3.y, tacc1);
            }

            const int cb = ks * 2 + khB;
            #pragma unroll
            for (int p = 0; p < 6; ++p) {
                uint32_t b0, b1, b2, b3;
                uint32_t addr = sb + (uint32_t)(nb[p] + ((cb ^ m7[p]) << 4));
                asm volatile("ldmatrix.sync.aligned.m8n8.x4.shared.b16 "
                             "{%0,%1,%2,%3}, [%4];"
                             : "=r"(b0), "=r"(b1), "=r"(b2), "=r"(b3) : "r"(addr));
                mma16816(acc[2 * p],     a0, a1, a2, a3, b0, b1);
                mma16816(acc[2 * p + 1], a0, a1, a2, a3, b2, b3);
            }
            {
                uint32_t b0, b1;
                uint32_t addr = sb + (uint32_t)(nb[6] + ((cb ^ m7[6]) << 4));
                asm volatile("ldmatrix.sync.aligned.m8n8.x2.shared.b16 "
                             "{%0,%1}, [%2];"
                             : "=r"(b0), "=r"(b1) : "r"(addr));
                mma16816(acc[12], a0, a1, a2, a3, b0, b1);
            }
        }
    }

    float myLoss = 0.0f;

    // ---- target scores: reduce over the 4 ctg lanes (k-slices)
    {
        float s0 = tacc0, s1 = tacc1;
        s0 += __shfl_xor_sync(0xffffffffu, s0, 1);
        s0 += __shfl_xor_sync(0xffffffffu, s0, 2);
        s1 += __shfl_xor_sync(0xffffffffu, s1, 1);
        s1 += __shfl_xor_sync(0xffffffffu, s1, 2);
        if (ctg == 0) {
            int t0 = warp * 16 + gid;
            myLoss += softplus_fast(-(s0 + sTC[t0]));
            myLoss += softplus_fast(-(s1 + sTC[t0 + 8]));
        }
    }

    // ---- epilogue: softplus over all 128x104 noise scores
    #pragma unroll
    for (int nt = 0; nt < NT; ++nt) {
        float c0 = sC[nt * 8 + ctg * 2];
        float c1 = sC[nt * 8 + ctg * 2 + 1];
        myLoss += softplus_fast(acc[nt][0] + c0);
        myLoss += softplus_fast(acc[nt][1] + c1);
        myLoss += softplus_fast(acc[nt][2] + c0);
        myLoss += softplus_fast(acc[nt][3] + c1);
    }

    // ---- block reduce
    #pragma unroll
    for (int d = 16; d >= 1; d >>= 1)
        myLoss += __shfl_xor_sync(0xffffffffu, myLoss, d);
    if (lane == 0) sRed[warp] = myLoss;
    __syncthreads();

    // ---- cross-block: last block reduces (single kernel)
    if (tid == 0) {
        float s = 0.f;
        #pragma unroll
        for (int w = 0; w < 8; ++w) s += sRed[w];
        g_partials[blockIdx.x] = s;
        __threadfence();
        unsigned n = atomicAdd(&g_counter, 1u);
        sFlag[0] = (n == GRID1 - 1) ? 1 : 0;
    }
    __syncthreads();
    if (sFlag[0]) {
        float v = (tid < GRID1) ? g_partials[tid] : 0.f;
        #pragma unroll
        for (int d = 16; d >= 1; d >>= 1)
            v += __shfl_xor_sync(0xffffffffu, v, d);
        if (lane == 0) sRed[warp] = v;
        __syncthreads();
        if (tid == 0) {
            float s = 0.f;
            #pragma unroll
            for (int w = 0; w < 8; ++w) s += sRed[w];
            out[0] = s * (1.0f / (float)NTOK);
            g_counter = 0u;                 // reset for next graph replay
        }
    }
}

extern "C" void kernel_launch(void* const* d_in, const int* in_sizes, int n_in,
                              void* d_out, int out_size) {
    (void)in_sizes; (void)n_in; (void)out_size;
    const float* inp       = (const float*)d_in[0];
    const float* emb       = (const float*)d_in[1];
    const float* bias      = (const float*)d_in[2];
    const float* logn      = (const float*)d_in[3];
    const int*   target    = (const int*)d_in[4];
    const int*   noise_idx = (const int*)d_in[5];

    float csub = logf(50257.0f) + logf(100.0f);   // NORM_TERM + LOG_NR

    cudaFuncSetAttribute(nce_hmma, cudaFuncAttributeMaxDynamicSharedMemorySize, SM_TOTAL);
    nce_hmma<<<GRID1, TPB, SM_TOTAL>>>(inp, emb, bias, logn, target, noise_idx,
                                       csub, (float*)d_out);
}